// round 11
// baseline (speedup 1.0000x reference)
#include <cuda_runtime.h>
#include <cuda_fp16.h>
#include <cstdint>
#include <cfloat>

// Problem shape (fixed by the dataset)
#define B_ROWS 4096
#define N_ROWS 32768
#define DIM    512

#define NSLICES 16
#define SLICE_N (N_ROWS / NSLICES)      // 2048
#define BM 128
#define BN 128
#define BK 32                           // K-chunk
#define MTILES (B_ROWS / BM)            // 32
#define NT     (SLICE_N / BN)           // 16 n-tiles per CTA
#define KCHUNKS 16                      // chunks per n-tile
#define STAGES 3
#define TOPK_CAP 10
#define NCONTRIB 8
#define NCAND (NSLICES * NCONTRIB * TOPK_CAP)   // 1280 candidates per row
#define ROWS2 (2 * B_ROWS)

// SW64-swizzled 64B rows: stage = A(128*32*2) + B(128*32*2) = 16KB
#define STAGE_BYTES 16384
#define RING_BYTES (STAGES * STAGE_BYTES)            // 49152
#define OFF_TOP RING_BYTES
#define SMEM_DYN (OFF_TOP + 4 * TOPK_CAP * 256 * 2)  // + 20KB topk = 69632

// ---- device scratch (no cudaMalloc allowed) ----
__device__ __half g_Xb[(size_t)B_ROWS * DIM];
__device__ __half g_Yb[(size_t)B_ROWS * DIM];
__device__ __half g_Zt[(size_t)N_ROWS * DIM];
__device__ __half g_Zr[(size_t)N_ROWS * DIM];
__device__ float g_top[(size_t)ROWS2 * NCAND];   // contiguous per (row,slice,contrib)
__device__ float g_acc[3];   // [0]=dot  [1]=fk0 sum  [2]=fk1 sum

// ---- PTX helpers ----
__device__ __forceinline__ uint32_t smem_u32(const void* p) {
    return (uint32_t)__cvta_generic_to_shared(p);
}
__device__ __forceinline__ void cp_async16(uint32_t dst, const void* src) {
    asm volatile("cp.async.cg.shared.global [%0], [%1], 16;\n" :: "r"(dst), "l"(src));
}
__device__ __forceinline__ void cp_commit() {
    asm volatile("cp.async.commit_group;\n");
}
__device__ __forceinline__ void cp_wait1() {
    asm volatile("cp.async.wait_group 1;\n" ::: "memory");
}
__device__ __forceinline__ void ldm_x4(uint32_t& r0, uint32_t& r1, uint32_t& r2, uint32_t& r3,
                                       uint32_t addr) {
    asm volatile("ldmatrix.sync.aligned.m8n8.x4.shared.b16 {%0,%1,%2,%3}, [%4];\n"
                 : "=r"(r0), "=r"(r1), "=r"(r2), "=r"(r3) : "r"(addr));
}
// fp16 accumulate: D regs = 2x f16x2 (rows g and g+8)
__device__ __forceinline__ void mma_f16(uint32_t& c0, uint32_t& c1,
                                        const uint32_t* a, uint32_t b0, uint32_t b1) {
    asm volatile(
        "mma.sync.aligned.m16n8k16.row.col.f16.f16.f16.f16 "
        "{%0,%1}, {%2,%3,%4,%5}, {%6,%7}, {%0,%1};\n"
        : "+r"(c0), "+r"(c1)
        : "r"(a[0]), "r"(a[1]), "r"(a[2]), "r"(a[3]), "r"(b0), "r"(b1));
}

// ---- tiny kernels ----
__global__ void zero_kernel() {
    if (threadIdx.x < 3) g_acc[threadIdx.x] = 0.0f;
}

__global__ void prep_kernel(const float* __restrict__ Xt, const float* __restrict__ Yt,
                            const float* __restrict__ Zt, const float* __restrict__ Zr) {
    size_t stride = (size_t)gridDim.x * blockDim.x;
    size_t i0 = (size_t)blockIdx.x * blockDim.x + threadIdx.x;
    const size_t nB4 = (size_t)B_ROWS * DIM / 4;
    const size_t nN4 = (size_t)N_ROWS * DIM / 4;
    const float4* X4 = (const float4*)Xt;
    const float4* Y4 = (const float4*)Yt;
    const float4* Zt4 = (const float4*)Zt;
    const float4* Zr4 = (const float4*)Zr;
    uint2* Xb2 = (uint2*)g_Xb;
    uint2* Yb2 = (uint2*)g_Yb;
    uint2* Zt2 = (uint2*)g_Zt;
    uint2* Zr2 = (uint2*)g_Zr;
    auto pack = [](float4 f) {
        __half2 lo = __floats2half2_rn(f.x, f.y);
        __half2 hi = __floats2half2_rn(f.z, f.w);
        return make_uint2(*(uint32_t*)&lo, *(uint32_t*)&hi);
    };
    for (size_t i = i0; i < nB4; i += stride) {
        Xb2[i] = pack(X4[i]);
        Yb2[i] = pack(Y4[i]);
    }
    for (size_t i = i0; i < nN4; i += stride) {
        Zt2[i] = pack(Zt4[i]);
        Zr2[i] = pack(Zr4[i]);
    }
}

__global__ void dot_kernel(const float* __restrict__ X, const float* __restrict__ Y) {
    float s = 0.0f;
    size_t stride = (size_t)gridDim.x * blockDim.x;
    const float4* X4 = (const float4*)X;
    const float4* Y4 = (const float4*)Y;
    for (size_t i = (size_t)blockIdx.x * blockDim.x + threadIdx.x;
         i < (size_t)B_ROWS * DIM / 4; i += stride) {
        float4 a = X4[i], b = Y4[i];
        s += a.x * b.x + a.y * b.y + a.z * b.z + a.w * b.w;
    }
    #pragma unroll
    for (int o = 16; o; o >>= 1) s += __shfl_xor_sync(0xFFFFFFFFu, s, o);
    __shared__ float ws[8];
    if ((threadIdx.x & 31) == 0) ws[threadIdx.x >> 5] = s;
    __syncthreads();
    if (threadIdx.x < 8) {
        float v = ws[threadIdx.x];
        #pragma unroll
        for (int o = 4; o; o >>= 1) v += __shfl_xor_sync(0xFFu, v, o);
        if (threadIdx.x == 0) atomicAdd(&g_acc[0], v);
    }
}

// ---- fused fp16 GEMM (A+B streamed, SW64 swizzle) + half top-10 in smem ----
// grid: x = MTILES*NSLICES, y = 2; block: 256 threads (8 warps, warp tile 32x64).
// 3 CTAs/SM target.
__global__ void __launch_bounds__(256, 3) gemm_topk_kernel() {
    extern __shared__ __align__(16) char dsm[];
    const uint32_t sbase = smem_u32(dsm);
    __half* sTop = (__half*)(dsm + OFF_TOP);   // [4*10][256] thread-private columns

    const int mat = blockIdx.y;
    const __half* __restrict__ Amat = mat ? g_Yb : g_Xb;
    const __half* __restrict__ Zmat = mat ? g_Zr : g_Zt;
    const int mblk  = blockIdx.x % MTILES;
    const int slice = blockIdx.x / MTILES;
    const int m0    = mblk * BM;
    const int nbase = slice * SLICE_N;

    const int tid = threadIdx.x;
    const int lane = tid & 31, wid = tid >> 5;
    const int warpM = wid >> 1, warpN = wid & 1;
    const int g = lane >> 2;

    // --- fragment smem offsets (SW64, 64B rows); ks=1 address = ks=0 ^ 32 ---
    const uint32_t acol = ((lane >> 4) & 1) * 16;
    const uint32_t bcol = ((lane >> 3) & 1) * 16;
    uint32_t aoffp[2], boffp[4];
    #pragma unroll
    for (int mf = 0; mf < 2; ++mf) {
        uint32_t row = warpM * 32 + mf * 16 + ((lane >> 3) & 1) * 8 + (lane & 7);
        uint32_t x = (row * 8) & 0x30;
        aoffp[mf] = row * 64 + (acol ^ x);
    }
    #pragma unroll
    for (int p = 0; p < 4; ++p) {
        uint32_t row = warpN * 64 + p * 16 + ((lane >> 4) & 1) * 8 + (lane & 7);
        uint32_t x = (row * 8) & 0x30;
        boffp[p] = row * 64 + (bcol ^ x) + 8192;   // B half of stage
    }

    // --- issue state: constant smem dsts, rolling global pointers ---
    const uint32_t r0 = (uint32_t)(tid >> 2);
    const uint32_t r1 = (uint32_t)((tid + 256) >> 2);
    const uint32_t c16 = (uint32_t)(tid & 3) * 16;
    const uint32_t dst0 = r0 * 64 + (c16 ^ ((r0 * 8) & 0x30));
    const uint32_t dst1 = r1 * 64 + (c16 ^ ((r1 * 8) & 0x30));
    const int ce = (tid & 3) * 8;

    const char* pa0 = (const char*)(Amat + (size_t)(m0 + r0) * DIM + ce);
    const char* pa1 = (const char*)(Amat + (size_t)(m0 + r1) * DIM + ce);
    const char* pb0 = (const char*)(Zmat + (size_t)(nbase + r0) * DIM + ce);
    const char* pb1 = (const char*)(Zmat + (size_t)(nbase + r1) * DIM + ce);

    auto issue4 = [&](uint32_t st) {       // st = absolute smem addr of stage
        cp_async16(st + dst0, pa0);
        cp_async16(st + 8192 + dst0, pb0);
        cp_async16(st + dst1, pa1);
        cp_async16(st + 8192 + dst1, pb1);
    };
    const intptr_t DSTEP = 64;
    const intptr_t DA_WRAP = -(15 * 64);
    const intptr_t DB_WRAP = (intptr_t)BN * DIM * 2 - 15 * 64;
    const uint32_t ring_end = sbase + RING_BYTES;

    // init smem top-k (half, -inf)
    const __half NEG_INF = __ushort_as_half((unsigned short)0xFC00u);
    #pragma unroll
    for (int i = 0; i < 4 * TOPK_CAP; ++i) sTop[i * 256 + tid] = NEG_INF;
    __half thr[4];
    int mi[4];
    #pragma unroll
    for (int rs = 0; rs < 4; ++rs) { thr[rs] = NEG_INF; mi[rs] = 0; }

    // prologue: chunks 0,1 into stages 0,1
    issue4(sbase);
    pa0 += DSTEP; pa1 += DSTEP; pb0 += DSTEP; pb1 += DSTEP;
    cp_commit();
    issue4(sbase + STAGE_BYTES);
    pa0 += DSTEP; pa1 += DSTEP; pb0 += DSTEP; pb1 += DSTEP;
    cp_commit();

    uint32_t stc = sbase;                      // consume stage (chunk gc)
    uint32_t stp = sbase + 2 * STAGE_BYTES;    // prefetch stage (chunk gc+2)

    uint32_t acc[2][8][2];                     // fp16x2 accumulators
    #pragma unroll
    for (int a = 0; a < 2; ++a)
        #pragma unroll
        for (int b = 0; b < 8; ++b) { acc[a][b][0] = 0u; acc[a][b][1] = 0u; }

    for (int nt = 0; nt < NT; ++nt) {
        const bool notlast = (nt < NT - 1);
        #pragma unroll
        for (int kt = 0; kt < KCHUNKS; ++kt) {
            cp_wait1();
            __syncthreads();
            // prefetch chunk local idx kt+2 (wraps at issued idx 15 -> kt==13)
            if (kt < 14 || notlast) {
                issue4(stp);
                if (kt == 13) {
                    pa0 += DA_WRAP; pa1 += DA_WRAP; pb0 += DB_WRAP; pb1 += DB_WRAP;
                } else {
                    pa0 += DSTEP; pa1 += DSTEP; pb0 += DSTEP; pb1 += DSTEP;
                }
            }
            cp_commit();

            #pragma unroll
            for (int ks = 0; ks < 2; ++ks) {
                uint32_t afr[2][4];
                #pragma unroll
                for (int mf = 0; mf < 2; ++mf) {
                    uint32_t addr = (stc + aoffp[mf]) ^ (ks * 32);
                    ldm_x4(afr[mf][0], afr[mf][1], afr[mf][2], afr[mf][3], addr);
                }
                #pragma unroll
                for (int p = 0; p < 4; ++p) {
                    uint32_t q0, q1, q2, q3;
                    uint32_t addr = (stc + boffp[p]) ^ (ks * 32);
                    ldm_x4(q0, q1, q2, q3, addr);
                    #pragma unroll
                    for (int mf = 0; mf < 2; ++mf) {
                        mma_f16(acc[mf][2 * p][0], acc[mf][2 * p][1], afr[mf], q0, q1);
                        mma_f16(acc[mf][2 * p + 1][0], acc[mf][2 * p + 1][1], afr[mf], q2, q3);
                    }
                }
            }

            if (kt == KCHUNKS - 1) {
                // fold accumulators into smem-backed per-row top-10s (half)
                #pragma unroll
                for (int mf = 0; mf < 2; ++mf) {
                    #pragma unroll
                    for (int h = 0; h < 2; ++h) {
                        const int rs = mf * 2 + h;
                        __half t = thr[rs];
                        int m = mi[rs];
                        #pragma unroll
                        for (int nf = 0; nf < 8; ++nf) {
                            uint32_t u = acc[mf][nf][h];
                            __half2 hv = *reinterpret_cast<__half2*>(&u);
                            #pragma unroll
                            for (int c = 0; c < 2; ++c) {
                                __half v = (c == 0) ? __low2half(hv) : __high2half(hv);
                                if (__hgt(v, t)) {
                                    sTop[(rs * TOPK_CAP + m) * 256 + tid] = v;
                                    t = __ushort_as_half((unsigned short)0x7C00u); // +inf
                                    m = 0;
                                    #pragma unroll
                                    for (int i = 0; i < TOPK_CAP; ++i) {
                                        __half w = sTop[(rs * TOPK_CAP + i) * 256 + tid];
                                        if (__hlt(w, t)) { t = w; m = i; }
                                    }
                                }
                            }
                        }
                        thr[rs] = t; mi[rs] = m;
                    }
                }
                #pragma unroll
                for (int a = 0; a < 2; ++a)
                    #pragma unroll
                    for (int b = 0; b < 8; ++b) { acc[a][b][0] = 0u; acc[a][b][1] = 0u; }
            }

            // advance rolling stage addrs
            stc += STAGE_BYTES; if (stc == ring_end) stc = sbase;
            stp += STAGE_BYTES; if (stp == ring_end) stp = sbase;
        }
    }

    // write candidates: contiguous per (row,slice,contrib) -> 40B bursts
    const int contrib = warpN * 4 + (lane & 3);
    #pragma unroll
    for (int mf = 0; mf < 2; ++mf) {
        #pragma unroll
        for (int h = 0; h < 2; ++h) {
            const int rs = mf * 2 + h;
            int row = m0 + warpM * 32 + mf * 16 + h * 8 + g;
            size_t base = ((((size_t)mat * B_ROWS + row) * NSLICES + slice) * NCONTRIB
                           + contrib) * TOPK_CAP;
            #pragma unroll
            for (int i = 0; i < TOPK_CAP; ++i)
                g_top[base + i] = __half2float(sTop[(rs * TOPK_CAP + i) * 256 + tid]);
        }
    }
}

// merge per-slice/per-thread top-10s into global top-k per row, sum, reduce
__global__ void merge_kernel(const int* __restrict__ knn) {
    int t = blockIdx.x * blockDim.x + threadIdx.x;
    if (t >= ROWS2) return;
    int k = *knn;
    if (k > TOPK_CAP) k = TOPK_CAP;
    if (k < 1) k = 1;
    const float* src = g_top + (size_t)t * NCAND;
    float best[TOPK_CAP];
    #pragma unroll
    for (int i = 0; i < TOPK_CAP; ++i) best[i] = -FLT_MAX;
    float thr = -FLT_MAX;
    int mi = 0;
    for (int j = 0; j < NCAND; ++j) {
        float v = src[j];
        if (v > thr) {
            best[mi] = v;
            thr = best[0]; mi = 0;
            for (int i = 1; i < k; ++i)
                if (best[i] < thr) { thr = best[i]; mi = i; }
        }
    }
    float s = 0.0f;
    for (int i = 0; i < k; ++i) s += best[i];
    int mat = t / B_ROWS;
    atomicAdd(&g_acc[1 + mat], s);
}

__global__ void final_kernel(float* __restrict__ out, const int* __restrict__ knn) {
    int k = *knn;
    if (k > TOPK_CAP) k = TOPK_CAP;
    if (k < 1) k = 1;
    // f = 2*dot - fk0 - fk1 ; out = -f/B = (fk0 + fk1 - 2*dot)/B
    out[0] = ((g_acc[1] + g_acc[2]) / (float)k - 2.0f * g_acc[0]) / (float)B_ROWS;
}

extern "C" void kernel_launch(void* const* d_in, const int* in_sizes, int n_in,
                              void* d_out, int out_size) {
    (void)in_sizes; (void)n_in; (void)out_size;
    // metadata order: X_src, X_trans, Y_tgt, Z_src, Z_trans, Z_tgt, knn
    const float* Xt = (const float*)d_in[1];
    const float* Yt = (const float*)d_in[2];
    const float* Zr = (const float*)d_in[4];
    const float* Zt = (const float*)d_in[5];
    const int* knn  = (const int*)d_in[6];
    float* out = (float*)d_out;

    cudaFuncSetAttribute(gemm_topk_kernel,
                         cudaFuncAttributeMaxDynamicSharedMemorySize, SMEM_DYN);

    zero_kernel<<<1, 32>>>();
    prep_kernel<<<4096, 256>>>(Xt, Yt, Zt, Zr);
    dot_kernel<<<1024, 256>>>(Xt, Yt);
    dim3 grid(MTILES * NSLICES, 2);
    gemm_topk_kernel<<<grid, 256, SMEM_DYN>>>();
    merge_kernel<<<(ROWS2 + 255) / 256, 256>>>(knn);
    final_kernel<<<1, 1>>>(out, knn);
}

// round 12
// speedup vs baseline: 1.8962x; 1.8962x over previous
#include <cuda_runtime.h>
#include <cuda_bf16.h>
#include <cstdint>
#include <cfloat>

// Problem shape (fixed by the dataset)
#define B_ROWS 4096
#define N_ROWS 32768
#define DIM    512

#define NSLICES 16
#define SLICE_N (N_ROWS / NSLICES)      // 2048
#define BM 128
#define BN 128
#define BK 64                           // K-chunk
#define MTILES (B_ROWS / BM)            // 32
#define NT     (SLICE_N / BN)           // 16 n-tiles per CTA
#define KCHUNKS (DIM / BK)              // 8 chunks per n-tile
#define STAGES 2
#define TOPK_CAP 10
#define NCONTRIB 8
#define NCAND (NSLICES * NCONTRIB * TOPK_CAP)   // 1280 candidates per row
#define ROWS2 (2 * B_ROWS)

// SW128-swizzled 128B rows: stage = A(128x128B) + B(128x128B) = 32KB
#define STAGE_BYTES 32768
#define OFF_BHALF 16384
#define OFF_TOP (STAGES * STAGE_BYTES)              // 65536
#define SMEM_DYN (OFF_TOP + 4 * TOPK_CAP * 256 * 4) // + 40KB topk = 106496

// ---- device scratch (no cudaMalloc allowed) ----
__device__ __nv_bfloat16 g_Xb[(size_t)B_ROWS * DIM];
__device__ __nv_bfloat16 g_Yb[(size_t)B_ROWS * DIM];
__device__ __nv_bfloat16 g_Zt[(size_t)N_ROWS * DIM];
__device__ __nv_bfloat16 g_Zr[(size_t)N_ROWS * DIM];
__device__ float g_top[(size_t)ROWS2 * NCAND];   // contiguous per (row,slice,contrib)
__device__ float g_acc[3];   // [0]=dot  [1]=fk0 sum  [2]=fk1 sum

// ---- PTX helpers ----
__device__ __forceinline__ uint32_t smem_u32(const void* p) {
    return (uint32_t)__cvta_generic_to_shared(p);
}
__device__ __forceinline__ void cp_async16(uint32_t dst, const void* src) {
    asm volatile("cp.async.cg.shared.global [%0], [%1], 16;\n" :: "r"(dst), "l"(src));
}
__device__ __forceinline__ void cp_commit() {
    asm volatile("cp.async.commit_group;\n");
}
__device__ __forceinline__ void cp_wait0() {
    asm volatile("cp.async.wait_group 0;\n" ::: "memory");
}
__device__ __forceinline__ void ldm_x4(uint32_t& r0, uint32_t& r1, uint32_t& r2, uint32_t& r3,
                                       uint32_t addr) {
    asm volatile("ldmatrix.sync.aligned.m8n8.x4.shared.b16 {%0,%1,%2,%3}, [%4];\n"
                 : "=r"(r0), "=r"(r1), "=r"(r2), "=r"(r3) : "r"(addr));
}
__device__ __forceinline__ void mma_bf16(float* c, const uint32_t* a, const uint32_t* b) {
    asm volatile(
        "mma.sync.aligned.m16n8k16.row.col.f32.bf16.bf16.f32 "
        "{%0,%1,%2,%3}, {%4,%5,%6,%7}, {%8,%9}, {%0,%1,%2,%3};\n"
        : "+f"(c[0]), "+f"(c[1]), "+f"(c[2]), "+f"(c[3])
        : "r"(a[0]), "r"(a[1]), "r"(a[2]), "r"(a[3]), "r"(b[0]), "r"(b[1]));
}

// ---- tiny kernels ----
__global__ void zero_kernel() {
    if (threadIdx.x < 3) g_acc[threadIdx.x] = 0.0f;
}

__global__ void prep_kernel(const float* __restrict__ Xt, const float* __restrict__ Yt,
                            const float* __restrict__ Zt, const float* __restrict__ Zr) {
    size_t stride = (size_t)gridDim.x * blockDim.x;
    size_t i0 = (size_t)blockIdx.x * blockDim.x + threadIdx.x;
    const size_t nB4 = (size_t)B_ROWS * DIM / 4;
    const size_t nN4 = (size_t)N_ROWS * DIM / 4;
    const float4* X4 = (const float4*)Xt;
    const float4* Y4 = (const float4*)Yt;
    const float4* Zt4 = (const float4*)Zt;
    const float4* Zr4 = (const float4*)Zr;
    uint2* Xb2 = (uint2*)g_Xb;
    uint2* Yb2 = (uint2*)g_Yb;
    uint2* Zt2 = (uint2*)g_Zt;
    uint2* Zr2 = (uint2*)g_Zr;
    auto pack = [](float4 f) {
        __nv_bfloat162 lo = __floats2bfloat162_rn(f.x, f.y);
        __nv_bfloat162 hi = __floats2bfloat162_rn(f.z, f.w);
        return make_uint2(*(uint32_t*)&lo, *(uint32_t*)&hi);
    };
    for (size_t i = i0; i < nB4; i += stride) {
        Xb2[i] = pack(X4[i]);
        Yb2[i] = pack(Y4[i]);
    }
    for (size_t i = i0; i < nN4; i += stride) {
        Zt2[i] = pack(Zt4[i]);
        Zr2[i] = pack(Zr4[i]);
    }
}

__global__ void dot_kernel(const float* __restrict__ X, const float* __restrict__ Y) {
    float s = 0.0f;
    size_t stride = (size_t)gridDim.x * blockDim.x;
    const float4* X4 = (const float4*)X;
    const float4* Y4 = (const float4*)Y;
    for (size_t i = (size_t)blockIdx.x * blockDim.x + threadIdx.x;
         i < (size_t)B_ROWS * DIM / 4; i += stride) {
        float4 a = X4[i], b = Y4[i];
        s += a.x * b.x + a.y * b.y + a.z * b.z + a.w * b.w;
    }
    #pragma unroll
    for (int o = 16; o; o >>= 1) s += __shfl_xor_sync(0xFFFFFFFFu, s, o);
    __shared__ float ws[8];
    if ((threadIdx.x & 31) == 0) ws[threadIdx.x >> 5] = s;
    __syncthreads();
    if (threadIdx.x < 8) {
        float v = ws[threadIdx.x];
        #pragma unroll
        for (int o = 4; o; o >>= 1) v += __shfl_xor_sync(0xFFu, v, o);
        if (threadIdx.x == 0) atomicAdd(&g_acc[0], v);
    }
}

// ---- fused bf16 GEMM (A+B streamed, BK=64, SW128, double buffer) + top-10 ----
// grid: x = MTILES*NSLICES, y = 2; block: 256 threads (8 warps, warp tile 32x64).
__global__ void __launch_bounds__(256, 2) gemm_topk_kernel() {
    extern __shared__ __align__(16) char dsm[];
    const uint32_t sbase = smem_u32(dsm);
    float* sTop = (float*)(dsm + OFF_TOP);   // [4*10][256] thread-private columns

    const int mat = blockIdx.y;
    const __nv_bfloat16* __restrict__ Amat = mat ? g_Yb : g_Xb;
    const __nv_bfloat16* __restrict__ Zmat = mat ? g_Zr : g_Zt;
    const int mblk  = blockIdx.x % MTILES;
    const int slice = blockIdx.x / MTILES;
    const int m0    = mblk * BM;
    const int nbase = slice * SLICE_N;

    const int tid = threadIdx.x;
    const int lane = tid & 31, wid = tid >> 5;
    const int warpM = wid >> 1, warpN = wid & 1;
    const int g = lane >> 2;

    // --- fragment smem offsets (SW128, 128B rows); addr(ks) = base ^ (ks*32) ---
    const uint32_t acol = ((lane >> 4) & 1) * 16;
    const uint32_t bcol = ((lane >> 3) & 1) * 16;
    uint32_t aoffp[2], boffp[4];
    #pragma unroll
    for (int mf = 0; mf < 2; ++mf) {
        uint32_t row = warpM * 32 + mf * 16 + ((lane >> 3) & 1) * 8 + (lane & 7);
        aoffp[mf] = row * 128 + (acol ^ ((row & 7) * 16));
    }
    #pragma unroll
    for (int p = 0; p < 4; ++p) {
        uint32_t row = warpN * 64 + p * 16 + ((lane >> 4) & 1) * 8 + (lane & 7);
        boffp[p] = row * 128 + (bcol ^ ((row & 7) * 16)) + OFF_BHALF;
    }

    // --- cp.async mapping: 4 A-segs + 4 B-segs of 16B per thread, const offsets ---
    const uint32_t t8 = (uint32_t)(tid >> 3);            // base row (0..31)
    const uint32_t c16 = (uint32_t)(tid & 7) * 16;       // byte col in 128B row
    const uint32_t dst0 = t8 * 128 + (c16 ^ ((t8 & 7) * 16));
    const int ce = (tid & 7) * 8;                        // elem col

    const char* pa = (const char*)(Amat + (size_t)(m0 + t8) * DIM + ce);
    const char* pb = (const char*)(Zmat + (size_t)(nbase + t8) * DIM + ce);

    auto issue = [&](uint32_t st) {       // st = absolute smem addr of stage
        #pragma unroll
        for (int i = 0; i < 4; ++i) {
            cp_async16(st + dst0 + i * 4096, pa + (size_t)i * 32768);
            cp_async16(st + OFF_BHALF + dst0 + i * 4096, pb + (size_t)i * 32768);
        }
    };
    const intptr_t DSTEP = 128;                               // BK*2 bytes
    const intptr_t DA_WRAP = -(intptr_t)((KCHUNKS - 1) * 128);
    const intptr_t DB_WRAP = (intptr_t)BN * DIM * 2 - (KCHUNKS - 1) * 128;

    // init smem top-k columns
    #pragma unroll
    for (int i = 0; i < 4 * TOPK_CAP; ++i) sTop[i * 256 + tid] = -FLT_MAX;
    float thr[4];
    int mi[4];
    #pragma unroll
    for (int rs = 0; rs < 4; ++rs) { thr[rs] = -FLT_MAX; mi[rs] = 0; }

    // prologue: chunk 0 into stage 0
    issue(sbase);
    pa += DSTEP; pb += DSTEP;
    cp_commit();

    float acc[2][8][4];
    #pragma unroll
    for (int a = 0; a < 2; ++a)
        #pragma unroll
        for (int b = 0; b < 8; ++b)
            #pragma unroll
            for (int c = 0; c < 4; ++c) acc[a][b][c] = 0.0f;

    for (int nt = 0; nt < NT; ++nt) {
        const bool notlast = (nt < NT - 1);
        #pragma unroll
        for (int kt = 0; kt < KCHUNKS; ++kt) {
            cp_wait0();                 // chunk kt landed
            __syncthreads();            // all warps done with the other stage
            if (kt < KCHUNKS - 1 || notlast) {
                issue(sbase + (uint32_t)(((kt + 1) & 1) * STAGE_BYTES));
                if (kt == KCHUNKS - 2) {   // issued local idx 7 -> wrap next
                    pa += DA_WRAP; pb += DB_WRAP;
                } else {
                    pa += DSTEP; pb += DSTEP;
                }
            }
            cp_commit();

            const uint32_t stc = sbase + (uint32_t)((kt & 1) * STAGE_BYTES);
            #pragma unroll
            for (int ks = 0; ks < 4; ++ks) {
                uint32_t afr[2][4];
                #pragma unroll
                for (int mf = 0; mf < 2; ++mf)
                    ldm_x4(afr[mf][0], afr[mf][1], afr[mf][2], afr[mf][3],
                           (stc + aoffp[mf]) ^ (uint32_t)(ks * 32));
                uint32_t bfr[8][2];
                #pragma unroll
                for (int p = 0; p < 4; ++p) {
                    uint32_t q0, q1, q2, q3;
                    ldm_x4(q0, q1, q2, q3, (stc + boffp[p]) ^ (uint32_t)(ks * 32));
                    bfr[2 * p][0] = q0;     bfr[2 * p][1] = q1;
                    bfr[2 * p + 1][0] = q2; bfr[2 * p + 1][1] = q3;
                }
                #pragma unroll
                for (int mf = 0; mf < 2; ++mf)
                    #pragma unroll
                    for (int nf = 0; nf < 8; ++nf)
                        mma_bf16(acc[mf][nf], afr[mf], bfr[nf]);
            }

            if (kt == KCHUNKS - 1) {
                // fold accumulators into smem-backed per-row top-10s
                #pragma unroll
                for (int mf = 0; mf < 2; ++mf) {
                    #pragma unroll
                    for (int h = 0; h < 2; ++h) {
                        const int rs = mf * 2 + h;
                        float t = thr[rs];
                        int m = mi[rs];
                        #pragma unroll
                        for (int nf = 0; nf < 8; ++nf) {
                            #pragma unroll
                            for (int c = 0; c < 2; ++c) {
                                float v = acc[mf][nf][h * 2 + c];
                                if (v > t) {
                                    sTop[(rs * TOPK_CAP + m) * 256 + tid] = v;
                                    t = FLT_MAX; m = 0;
                                    #pragma unroll
                                    for (int i = 0; i < TOPK_CAP; ++i) {
                                        float u = sTop[(rs * TOPK_CAP + i) * 256 + tid];
                                        if (u < t) { t = u; m = i; }
                                    }
                                }
                            }
                        }
                        thr[rs] = t; mi[rs] = m;
                    }
                }
                #pragma unroll
                for (int a = 0; a < 2; ++a)
                    #pragma unroll
                    for (int b = 0; b < 8; ++b)
                        #pragma unroll
                        for (int c = 0; c < 4; ++c) acc[a][b][c] = 0.0f;
            }
        }
    }

    // write candidates: contiguous per (row,slice,contrib) -> 40B bursts
    const int contrib = warpN * 4 + (lane & 3);
    #pragma unroll
    for (int mf = 0; mf < 2; ++mf) {
        #pragma unroll
        for (int h = 0; h < 2; ++h) {
            const int rs = mf * 2 + h;
            int row = m0 + warpM * 32 + mf * 16 + h * 8 + g;
            size_t base = ((((size_t)mat * B_ROWS + row) * NSLICES + slice) * NCONTRIB
                           + contrib) * TOPK_CAP;
            #pragma unroll
            for (int i = 0; i < TOPK_CAP; ++i)
                g_top[base + i] = sTop[(rs * TOPK_CAP + i) * 256 + tid];
        }
    }
}

// merge: one WARP per row, coalesced reads, warp-wide top-k-of-union
__global__ void merge_kernel(const int* __restrict__ knn) {
    const int lane = threadIdx.x & 31;
    const int row = blockIdx.x * 8 + (threadIdx.x >> 5);
    if (row >= ROWS2) return;
    int k = *knn;
    if (k > TOPK_CAP) k = TOPK_CAP;
    if (k < 1) k = 1;
    const float* src = g_top + (size_t)row * NCAND;

    // per-lane top-10 of its 40 strided (coalesced across lanes) values
    float best[TOPK_CAP];
    #pragma unroll
    for (int i = 0; i < TOPK_CAP; ++i) best[i] = -FLT_MAX;
    float thr = -FLT_MAX;
    int mi = 0;
    #pragma unroll 4
    for (int j = 0; j < NCAND / 32; ++j) {
        float v = src[lane + 32 * j];
        if (v > thr) {
            best[mi] = v;
            thr = FLT_MAX; mi = 0;
            #pragma unroll
            for (int i = 0; i < TOPK_CAP; ++i)
                if (best[i] < thr) { thr = best[i]; mi = i; }
        }
    }

    // k rounds of warp-max over remaining lane candidates
    unsigned used = 0;
    float sum = 0.0f;
    for (int r = 0; r < k; ++r) {
        float m = -FLT_MAX;
        int idx = 0;
        #pragma unroll
        for (int i = 0; i < TOPK_CAP; ++i)
            if (!((used >> i) & 1u) && best[i] > m) { m = best[i]; idx = i; }
        float wm = m;
        #pragma unroll
        for (int o = 16; o; o >>= 1) wm = fmaxf(wm, __shfl_xor_sync(0xFFFFFFFFu, wm, o));
        unsigned bal = __ballot_sync(0xFFFFFFFFu, m == wm);
        if (lane == (int)(__ffs(bal) - 1)) used |= 1u << idx;
        sum += wm;
    }
    if (lane == 0) atomicAdd(&g_acc[1 + row / B_ROWS], sum);
}

__global__ void final_kernel(float* __restrict__ out, const int* __restrict__ knn) {
    int k = *knn;
    if (k > TOPK_CAP) k = TOPK_CAP;
    if (k < 1) k = 1;
    // f = 2*dot - fk0 - fk1 ; out = -f/B = (fk0 + fk1 - 2*dot)/B
    out[0] = ((g_acc[1] + g_acc[2]) / (float)k - 2.0f * g_acc[0]) / (float)B_ROWS;
}

extern "C" void kernel_launch(void* const* d_in, const int* in_sizes, int n_in,
                              void* d_out, int out_size) {
    (void)in_sizes; (void)n_in; (void)out_size;
    // metadata order: X_src, X_trans, Y_tgt, Z_src, Z_trans, Z_tgt, knn
    const float* Xt = (const float*)d_in[1];
    const float* Yt = (const float*)d_in[2];
    const float* Zr = (const float*)d_in[4];
    const float* Zt = (const float*)d_in[5];
    const int* knn  = (const int*)d_in[6];
    float* out = (float*)d_out;

    cudaFuncSetAttribute(gemm_topk_kernel,
                         cudaFuncAttributeMaxDynamicSharedMemorySize, SMEM_DYN);

    zero_kernel<<<1, 32>>>();
    prep_kernel<<<4096, 256>>>(Xt, Yt, Zt, Zr);
    dot_kernel<<<1024, 256>>>(Xt, Yt);
    dim3 grid(MTILES * NSLICES, 2);
    gemm_topk_kernel<<<grid, 256, SMEM_DYN>>>();
    merge_kernel<<<ROWS2 / 8, 256>>>(knn);
    final_kernel<<<1, 1>>>(out, knn);
}